// round 1
// baseline (speedup 1.0000x reference)
#include <cuda_runtime.h>

#define B_   2
#define SQ_  2048
#define SKV_ 2048
#define H_   1024
#define NH_  16
#define HD_  64

// Scratch (no cudaMalloc allowed): Q/K/V in [B,NH,S,HD], ctx in [B,SQ,H]
__device__ float g_q[(size_t)B_ * NH_ * SQ_ * HD_];
__device__ float g_k[(size_t)B_ * NH_ * SKV_ * HD_];
__device__ float g_v[(size_t)B_ * NH_ * SKV_ * HD_];
__device__ float g_ctx[(size_t)B_ * SQ_ * H_];

// ---------------------------------------------------------------------------
// Projection GEMM: out[m][n] = sum_k A[m][k] * W[n][k] + bias[n]
// A: [M, K] row-major, W: [N, K] row-major (i.e. x @ W^T), M = 4096 fixed by grid.
// split==1 -> write to [B, NH, S, HD] split-head layout; else flat [M, N].
// 128x128 tile, BK=8, 256 threads, 8x8 per-thread, double-buffered smem.
// ---------------------------------------------------------------------------
__global__ __launch_bounds__(256, 2)
void proj_kernel(const float* __restrict__ A, const float* __restrict__ W,
                 const float* __restrict__ bias, float* __restrict__ out,
                 int K, int N, int split)
{
    __shared__ float As[2][8][132];   // k-major: As[buf][k][m]
    __shared__ float Bs[2][8][132];   // k-major: Bs[buf][k][n]

    const int tid = threadIdx.x;
    const int tx = tid & 15, ty = tid >> 4;
    const int bm = blockIdx.y * 128;
    const int bn = blockIdx.x * 128;

    // global->smem load mapping: each thread loads one float4 of A and W
    const int lr = tid >> 1;          // row 0..127 within tile
    const int lk = (tid & 1) << 2;    // k offset 0 or 4
    const float* Ag = A + (size_t)(bm + lr) * K + lk;
    const float* Wg = W + (size_t)(bn + lr) * K + lk;

    float acc[8][8];
#pragma unroll
    for (int i = 0; i < 8; i++)
#pragma unroll
        for (int j = 0; j < 8; j++) acc[i][j] = 0.f;

    float4 ra = *(const float4*)Ag;
    float4 rb = *(const float4*)Wg;
    As[0][lk + 0][lr] = ra.x; As[0][lk + 1][lr] = ra.y;
    As[0][lk + 2][lr] = ra.z; As[0][lk + 3][lr] = ra.w;
    Bs[0][lk + 0][lr] = rb.x; Bs[0][lk + 1][lr] = rb.y;
    Bs[0][lk + 2][lr] = rb.z; Bs[0][lk + 3][lr] = rb.w;
    __syncthreads();

    const int nt = K >> 3;
    for (int t = 0; t < nt; t++) {
        const int cur = t & 1;
        if (t + 1 < nt) {
            ra = *(const float4*)(Ag + ((t + 1) << 3));
            rb = *(const float4*)(Wg + ((t + 1) << 3));
        }
#pragma unroll
        for (int kk = 0; kk < 8; kk++) {
            float a[8], bf[8];
            *(float4*)&a[0]  = *(const float4*)&As[cur][kk][ty * 8];
            *(float4*)&a[4]  = *(const float4*)&As[cur][kk][ty * 8 + 4];
            *(float4*)&bf[0] = *(const float4*)&Bs[cur][kk][tx * 8];
            *(float4*)&bf[4] = *(const float4*)&Bs[cur][kk][tx * 8 + 4];
#pragma unroll
            for (int i = 0; i < 8; i++)
#pragma unroll
                for (int j = 0; j < 8; j++)
                    acc[i][j] = fmaf(a[i], bf[j], acc[i][j]);
        }
        if (t + 1 < nt) {
            const int nx = cur ^ 1;
            As[nx][lk + 0][lr] = ra.x; As[nx][lk + 1][lr] = ra.y;
            As[nx][lk + 2][lr] = ra.z; As[nx][lk + 3][lr] = ra.w;
            Bs[nx][lk + 0][lr] = rb.x; Bs[nx][lk + 1][lr] = rb.y;
            Bs[nx][lk + 2][lr] = rb.z; Bs[nx][lk + 3][lr] = rb.w;
        }
        __syncthreads();
    }

    float bcol[8];
#pragma unroll
    for (int j = 0; j < 8; j++)
        bcol[j] = bias ? bias[bn + tx * 8 + j] : 0.f;

#pragma unroll
    for (int i = 0; i < 8; i++) {
        const int m = bm + ty * 8 + i;
#pragma unroll
        for (int j4 = 0; j4 < 2; j4++) {
            const int n = bn + tx * 8 + j4 * 4;
            float4 r;
            r.x = acc[i][j4 * 4 + 0] + bcol[j4 * 4 + 0];
            r.y = acc[i][j4 * 4 + 1] + bcol[j4 * 4 + 1];
            r.z = acc[i][j4 * 4 + 2] + bcol[j4 * 4 + 2];
            r.w = acc[i][j4 * 4 + 3] + bcol[j4 * 4 + 3];
            if (split) {
                const int bb = m >> 11;        // / SQ_
                const int ss = m & 2047;       // % SQ_
                const int hh = n >> 6;         // / HD_
                const int dd = n & 63;         // % HD_
                *(float4*)(out + (((size_t)bb * NH_ + hh) * SQ_ + ss) * HD_ + dd) = r;
            } else {
                *(float4*)(out + (size_t)m * N + n) = r;
            }
        }
    }
}

// ---------------------------------------------------------------------------
// Flash attention (fp32): per block: 128 q rows for one (b, h).
// S tile 128x128, online softmax, O accumulated in registers.
// Thread layout 16x16: S rows ty*8+i, S cols tx*8+j; O rows ty*8+i, d cols tx*4+j.
// ---------------------------------------------------------------------------
#define ATTN_SMEM_FLOATS (64 * 132 + 64 * 132 + 128 * 68 + 128 * 132)
#define ATTN_SMEM_BYTES  (ATTN_SMEM_FLOATS * 4)

__global__ __launch_bounds__(256, 1)
void attn_kernel(const float* __restrict__ Q, const float* __restrict__ Kin,
                 const float* __restrict__ Vin, const float* __restrict__ mask,
                 float* __restrict__ ctx)
{
    extern __shared__ float sm[];
    float* Qs = sm;                     // [64 d][132]  (transposed, pre-scaled)
    float* Ks = sm + 64 * 132;          // [64 d][132]  (transposed)
    float* Vs = sm + 2 * 64 * 132;      // [128 j][68]
    float* Ps = Vs + 128 * 68;          // [128 r][132]

    const int tid = threadIdx.x;
    const int tx = tid & 15, ty = tid >> 4;
    const int q0 = blockIdx.x << 7;
    const int h  = blockIdx.y;
    const int b  = blockIdx.z;

    const float* Qp = Q   + ((size_t)(b * NH_ + h) * SQ_ + q0) * HD_;
    const float* Kp = Kin + (size_t)(b * NH_ + h) * SKV_ * HD_;
    const float* Vp = Vin + (size_t)(b * NH_ + h) * SKV_ * HD_;
    const float* Mp = mask + ((size_t)b * SQ_ + q0) * SKV_;

    // Load Q tile transposed, pre-scaled by 1/sqrt(HD) = 0.125
    for (int idx = tid; idx < 128 * 16; idx += 256) {
        const int r = idx >> 4;
        const int d = (idx & 15) << 2;
        float4 v = *(const float4*)(Qp + r * HD_ + d);
        Qs[(d + 0) * 132 + r] = v.x * 0.125f;
        Qs[(d + 1) * 132 + r] = v.y * 0.125f;
        Qs[(d + 2) * 132 + r] = v.z * 0.125f;
        Qs[(d + 3) * 132 + r] = v.w * 0.125f;
    }

    float m_i[8], l_i[8], o[8][4];
#pragma unroll
    for (int i = 0; i < 8; i++) {
        m_i[i] = -1e30f;
        l_i[i] = 0.f;
        o[i][0] = o[i][1] = o[i][2] = o[i][3] = 0.f;
    }

    for (int t = 0; t < SKV_ / 128; t++) {
        __syncthreads();  // prev iteration's PV reads of Vs/Ps are done
        const float* Kt = Kp + (size_t)(t << 7) * HD_;
        const float* Vt = Vp + (size_t)(t << 7) * HD_;
        for (int idx = tid; idx < 128 * 16; idx += 256) {
            const int r = idx >> 4;
            const int d = (idx & 15) << 2;
            float4 v = *(const float4*)(Kt + r * HD_ + d);
            Ks[(d + 0) * 132 + r] = v.x;
            Ks[(d + 1) * 132 + r] = v.y;
            Ks[(d + 2) * 132 + r] = v.z;
            Ks[(d + 3) * 132 + r] = v.w;
            *(float4*)(Vs + r * 68 + d) = *(const float4*)(Vt + r * HD_ + d);
        }
        __syncthreads();

        // S = (Q*scale) @ K^T
        float s[8][8];
#pragma unroll
        for (int i = 0; i < 8; i++)
#pragma unroll
            for (int j = 0; j < 8; j++) s[i][j] = 0.f;

#pragma unroll 4
        for (int d = 0; d < 64; d++) {
            float a[8], kb[8];
            *(float4*)&a[0]  = *(const float4*)&Qs[d * 132 + ty * 8];
            *(float4*)&a[4]  = *(const float4*)&Qs[d * 132 + ty * 8 + 4];
            *(float4*)&kb[0] = *(const float4*)&Ks[d * 132 + tx * 8];
            *(float4*)&kb[4] = *(const float4*)&Ks[d * 132 + tx * 8 + 4];
#pragma unroll
            for (int i = 0; i < 8; i++)
#pragma unroll
                for (int j = 0; j < 8; j++)
                    s[i][j] = fmaf(a[i], kb[j], s[i][j]);
        }

        // mask + online softmax + write P to smem
#pragma unroll
        for (int i = 0; i < 8; i++) {
            const float* mrow = Mp + (size_t)(ty * 8 + i) * SKV_ + (t << 7) + tx * 8;
            float4 m0 = *(const float4*)mrow;
            float4 m1 = *(const float4*)(mrow + 4);
            s[i][0] += (m0.x - 1.f) * 10000.f;
            s[i][1] += (m0.y - 1.f) * 10000.f;
            s[i][2] += (m0.z - 1.f) * 10000.f;
            s[i][3] += (m0.w - 1.f) * 10000.f;
            s[i][4] += (m1.x - 1.f) * 10000.f;
            s[i][5] += (m1.y - 1.f) * 10000.f;
            s[i][6] += (m1.z - 1.f) * 10000.f;
            s[i][7] += (m1.w - 1.f) * 10000.f;

            float mx = s[i][0];
#pragma unroll
            for (int j = 1; j < 8; j++) mx = fmaxf(mx, s[i][j]);
            // reduce across the 16 tx lanes (lane = (ty&1)*16 + tx)
            mx = fmaxf(mx, __shfl_xor_sync(0xffffffffu, mx, 1));
            mx = fmaxf(mx, __shfl_xor_sync(0xffffffffu, mx, 2));
            mx = fmaxf(mx, __shfl_xor_sync(0xffffffffu, mx, 4));
            mx = fmaxf(mx, __shfl_xor_sync(0xffffffffu, mx, 8));

            const float newm = fmaxf(m_i[i], mx);
            const float alpha = __expf(m_i[i] - newm);
            m_i[i] = newm;

            float rs = 0.f;
#pragma unroll
            for (int j = 0; j < 8; j++) {
                s[i][j] = __expf(s[i][j] - newm);
                rs += s[i][j];
            }
            rs += __shfl_xor_sync(0xffffffffu, rs, 1);
            rs += __shfl_xor_sync(0xffffffffu, rs, 2);
            rs += __shfl_xor_sync(0xffffffffu, rs, 4);
            rs += __shfl_xor_sync(0xffffffffu, rs, 8);

            l_i[i] = l_i[i] * alpha + rs;
            o[i][0] *= alpha; o[i][1] *= alpha; o[i][2] *= alpha; o[i][3] *= alpha;

            float4 p0 = make_float4(s[i][0], s[i][1], s[i][2], s[i][3]);
            float4 p1 = make_float4(s[i][4], s[i][5], s[i][6], s[i][7]);
            *(float4*)&Ps[(ty * 8 + i) * 132 + tx * 8]     = p0;
            *(float4*)&Ps[(ty * 8 + i) * 132 + tx * 8 + 4] = p1;
        }
        __syncthreads();

        // O += P @ V  (P reads are warp-broadcast: address independent of tx)
#pragma unroll 2
        for (int j = 0; j < 128; j++) {
            const float4 vv = *(const float4*)&Vs[j * 68 + tx * 4];
#pragma unroll
            for (int i = 0; i < 8; i++) {
                const float p = Ps[(ty * 8 + i) * 132 + j];
                o[i][0] = fmaf(p, vv.x, o[i][0]);
                o[i][1] = fmaf(p, vv.y, o[i][1]);
                o[i][2] = fmaf(p, vv.z, o[i][2]);
                o[i][3] = fmaf(p, vv.w, o[i][3]);
            }
        }
    }

    // normalize and write ctx[b][q][h*64+d]
#pragma unroll
    for (int i = 0; i < 8; i++) {
        const float inv = 1.f / l_i[i];
        float4 r = make_float4(o[i][0] * inv, o[i][1] * inv, o[i][2] * inv, o[i][3] * inv);
        *(float4*)(ctx + ((size_t)b * SQ_ + q0 + ty * 8 + i) * H_ + h * HD_ + tx * 4) = r;
    }
}

// ---------------------------------------------------------------------------
extern "C" void kernel_launch(void* const* d_in, const int* in_sizes, int n_in,
                              void* d_out, int out_size)
{
    (void)in_sizes; (void)n_in; (void)out_size;
    const float* xq  = (const float*)d_in[0];  // query_states   [B,SQ,H]
    const float* xkv = (const float*)d_in[1];  // key_value_states [B,SKV,H]
    const float* msk = (const float*)d_in[2];  // attention_mask [B,SQ,SKV]
    const float* Wq  = (const float*)d_in[3];
    const float* bq  = (const float*)d_in[4];
    const float* Wk  = (const float*)d_in[5];
    const float* Wv  = (const float*)d_in[6];
    const float* bv  = (const float*)d_in[7];
    const float* Wo  = (const float*)d_in[8];
    const float* bo  = (const float*)d_in[9];
    float* out = (float*)d_out;

    float *q, *k, *v, *ctx;
    cudaGetSymbolAddress((void**)&q,   g_q);
    cudaGetSymbolAddress((void**)&k,   g_k);
    cudaGetSymbolAddress((void**)&v,   g_v);
    cudaGetSymbolAddress((void**)&ctx, g_ctx);

    cudaFuncSetAttribute(attn_kernel, cudaFuncAttributeMaxDynamicSharedMemorySize,
                         ATTN_SMEM_BYTES);

    dim3 pg(H_ / 128, (B_ * SQ_) / 128);  // (8, 32)
    proj_kernel<<<pg, 256>>>(xq,  Wq, bq,      q,   H_, H_, 1);
    proj_kernel<<<pg, 256>>>(xkv, Wk, nullptr, k,   H_, H_, 1);
    proj_kernel<<<pg, 256>>>(xkv, Wv, bv,      v,   H_, H_, 1);
    attn_kernel<<<dim3(SQ_ / 128, NH_, B_), 256, ATTN_SMEM_BYTES>>>(q, k, v, msk, ctx);
    proj_kernel<<<pg, 256>>>(ctx, Wo, bo,      out, H_, H_, 0);
}

// round 6
// speedup vs baseline: 1.1922x; 1.1922x over previous
#include <cuda_runtime.h>
#include <cuda_bf16.h>
#include <cstdint>

#define B_   2
#define SQ_  2048
#define SKV_ 2048
#define H_   1024
#define NH_  16
#define HD_  64
#define K_   1024
#define M_   4096   /* B_*SQ_ rows into every projection */

// ===========================================================================
// Helpers
// ===========================================================================
__device__ __forceinline__ uint32_t smem_to_u32(const void* p) {
    uint32_t a;
    asm("{ .reg .u64 t; cvta.to.shared.u64 t, %1; cvt.u32.u64 %0, t; }"
        : "=r"(a) : "l"(p));
    return a;
}
__device__ __forceinline__ void ldsm4(uint32_t* r, uint32_t addr) {
    asm volatile("ldmatrix.sync.aligned.m8n8.x4.shared.b16 {%0,%1,%2,%3}, [%4];"
                 : "=r"(r[0]), "=r"(r[1]), "=r"(r[2]), "=r"(r[3]) : "r"(addr));
}
__device__ __forceinline__ void mma16816(float* d, const uint32_t* a, const uint32_t* b) {
    asm volatile("mma.sync.aligned.m16n8k16.row.col.f32.bf16.bf16.f32 "
                 "{%0,%1,%2,%3}, {%4,%5,%6,%7}, {%8,%9}, {%0,%1,%2,%3};"
                 : "+f"(d[0]), "+f"(d[1]), "+f"(d[2]), "+f"(d[3])
                 : "r"(a[0]), "r"(a[1]), "r"(a[2]), "r"(a[3]), "r"(b[0]), "r"(b[1]));
}
#define SMEM_SWIZZLE_128B(off) ((off) ^ (((off) >> 3) & 0x70))

// ===========================================================================
// Scratch (__device__ globals; no cudaMalloc allowed)
// ===========================================================================
__device__ float g_q[(size_t)B_ * NH_ * SQ_ * HD_];
__device__ float g_k[(size_t)B_ * NH_ * SKV_ * HD_];
__device__ float g_v[(size_t)B_ * NH_ * SKV_ * HD_];
__device__ float g_ctx[(size_t)B_ * SQ_ * H_];

__device__ __nv_bfloat16 g_xq_h[(size_t)M_ * K_],  g_xq_l[(size_t)M_ * K_];
__device__ __nv_bfloat16 g_xkv_h[(size_t)M_ * K_], g_xkv_l[(size_t)M_ * K_];
__device__ __nv_bfloat16 g_wq_h[(size_t)H_ * K_],  g_wq_l[(size_t)H_ * K_];
__device__ __nv_bfloat16 g_wk_h[(size_t)H_ * K_],  g_wk_l[(size_t)H_ * K_];
__device__ __nv_bfloat16 g_wv_h[(size_t)H_ * K_],  g_wv_l[(size_t)H_ * K_];
__device__ __nv_bfloat16 g_wo_h[(size_t)H_ * K_],  g_wo_l[(size_t)H_ * K_];
__device__ __nv_bfloat16 g_ctx_h[(size_t)M_ * K_], g_ctx_l[(size_t)M_ * K_];

// ===========================================================================
// fp32 -> (bf16 hi, bf16 lo) split kernel
// ===========================================================================
__global__ __launch_bounds__(256)
void split_kernel(const float* __restrict__ x, __nv_bfloat16* __restrict__ hi,
                  __nv_bfloat16* __restrict__ lo, int n)
{
    int i = (blockIdx.x * 256 + threadIdx.x) * 4;
    if (i >= n) return;
    float4 v = *(const float4*)(x + i);
    float f[4] = {v.x, v.y, v.z, v.w};
    unsigned short hs[4], ls[4];
#pragma unroll
    for (int j = 0; j < 4; j++) {
        __nv_bfloat16 h = __float2bfloat16(f[j]);
        __nv_bfloat16 l = __float2bfloat16(f[j] - __bfloat162float(h));
        hs[j] = *(unsigned short*)&h;
        ls[j] = *(unsigned short*)&l;
    }
    *(ushort4*)((unsigned short*)hi + i) = make_ushort4(hs[0], hs[1], hs[2], hs[3]);
    *(ushort4*)((unsigned short*)lo + i) = make_ushort4(ls[0], ls[1], ls[2], ls[3]);
}

// ===========================================================================
// mma.sync projection GEMM, split-bf16 (hi*hi + hi*lo + lo*hi), fp32 accum.
// out[m][n] = sum_k A[m][k]*W[n][k] + bias[n].  CTA tile 128x128, K-step 64.
// 8 warps, each 64x32 (4x4 of m16n8k16).
// ===========================================================================
#define OFF_AH 0
#define OFF_AL (OFF_AH + 16384)
#define OFF_BH (OFF_AL + 16384)
#define OFF_BL (OFF_BH + 16384)
#define PROJ_SMEM (OFF_BL + 16384)   /* 65536 bytes */

__global__ __launch_bounds__(256, 1)
void proj_mma(const __nv_bfloat16* __restrict__ Ah, const __nv_bfloat16* __restrict__ Al,
              const __nv_bfloat16* __restrict__ Bh, const __nv_bfloat16* __restrict__ Bl,
              const float* __restrict__ bias, float* __restrict__ out, int split)
{
    extern __shared__ char smem[];
    const uint32_t sb = smem_to_u32(smem);
    const int tid  = threadIdx.x;
    const int wid  = tid >> 5, lane = tid & 31;
    const int bn = blockIdx.x * 128;
    const int bm = blockIdx.y * 128;
    const int wm = (wid >> 2) * 64;   // warp m offset in tile
    const int wn = (wid & 3) * 32;    // warp n offset in tile

    float acc[4][4][4];
#pragma unroll
    for (int i = 0; i < 4; i++)
#pragma unroll
        for (int j = 0; j < 4; j++)
#pragma unroll
            for (int r = 0; r < 4; r++) acc[i][j][r] = 0.f;

    // ldmatrix lane geometry.
    const int a_rl  = (lane & 7) + ((lane >> 3) & 1) * 8;  // row within m16
    const int a_kc8 = (lane >> 4) * 8;                     // k sub-offset
    const int b_rl  = (lane & 7) + (lane >> 4) * 8;        // row within n16 pair
    const int b_kc8 = ((lane >> 3) & 1) * 8;

    // Per-row swizzle: byte = row*128 + kcol*2; kcol*2 < 128 so swizzle XOR
    // constant = (row&7)<<4 for the whole row.
    uint32_t aRow[4], aXor[4];
#pragma unroll
    for (int i = 0; i < 4; i++) {
        const int r = wm + i * 16 + a_rl;
        aRow[i] = (uint32_t)r * 128u;
        aXor[i] = (uint32_t)((r & 7) << 4);
    }
    uint32_t bRow[2], bXor[2];
#pragma unroll
    for (int jp = 0; jp < 2; jp++) {
        const int r = wn + jp * 16 + b_rl;
        bRow[jp] = (uint32_t)r * 128u;
        bXor[jp] = (uint32_t)((r & 7) << 4);
    }

    for (int step = 0; step < 16; step++) {
        const int k0g = step * 64;
        // fill 4 tiles: 128 rows x 64 bf16 (128B/row), SW128-swizzled
        for (int idx = tid; idx < 1024; idx += 256) {
            const int r  = idx >> 3;
            const int cu = idx & 7;
            const uint32_t so = SMEM_SWIZZLE_128B((uint32_t)(r * 128 + cu * 16));
            const size_t ga = (size_t)(bm + r) * K_ + k0g + cu * 8;
            const size_t gb = (size_t)(bn + r) * K_ + k0g + cu * 8;
            *(uint4*)(smem + OFF_AH + so) = *(const uint4*)(Ah + ga);
            *(uint4*)(smem + OFF_AL + so) = *(const uint4*)(Al + ga);
            *(uint4*)(smem + OFF_BH + so) = *(const uint4*)(Bh + gb);
            *(uint4*)(smem + OFF_BL + so) = *(const uint4*)(Bl + gb);
        }
        __syncthreads();

#pragma unroll
        for (int kk = 0; kk < 4; kk++) {
            const uint32_t ka = (uint32_t)(2 * (kk * 16 + a_kc8));
            const uint32_t kb = (uint32_t)(2 * (kk * 16 + b_kc8));

            uint32_t ah[4][4], al[4][4];
#pragma unroll
            for (int i = 0; i < 4; i++) {
                const uint32_t off = aRow[i] + (ka ^ aXor[i]);
                ldsm4(ah[i], sb + OFF_AH + off);
                ldsm4(al[i], sb + OFF_AL + off);
            }
            uint32_t bh[2][4], bl[2][4];
#pragma unroll
            for (int jp = 0; jp < 2; jp++) {
                const uint32_t off = bRow[jp] + (kb ^ bXor[jp]);
                ldsm4(bh[jp], sb + OFF_BH + off);
                ldsm4(bl[jp], sb + OFF_BL + off);
            }

#pragma unroll
            for (int i = 0; i < 4; i++)
#pragma unroll
                for (int j = 0; j < 4; j++) {
                    const uint32_t* fbh = &bh[j >> 1][(j & 1) * 2];
                    const uint32_t* fbl = &bl[j >> 1][(j & 1) * 2];
                    mma16816(acc[i][j], ah[i], fbh);
                    mma16816(acc[i][j], ah[i], fbl);
                    mma16816(acc[i][j], al[i], fbh);
                }
        }
        __syncthreads();
    }

    // epilogue: thread t owns rows (m, m+8), cols (n, n+1) per tile
    const int mt = lane >> 2;
    const int nt = (lane & 3) * 2;
#pragma unroll
    for (int i = 0; i < 4; i++) {
        const int m0 = bm + wm + i * 16 + mt;
#pragma unroll
        for (int j = 0; j < 4; j++) {
            const int n = bn + wn + j * 8 + nt;
            float b0 = 0.f, b1 = 0.f;
            if (bias) { b0 = bias[n]; b1 = bias[n + 1]; }
            float2 v0 = make_float2(acc[i][j][0] + b0, acc[i][j][1] + b1);
            float2 v1 = make_float2(acc[i][j][2] + b0, acc[i][j][3] + b1);
            if (split) {
                const int hh = n >> 6, dd = n & 63;
                const int bb0 = m0 >> 11, ss0 = m0 & 2047;
                *(float2*)(out + (((size_t)bb0 * NH_ + hh) * SQ_ + ss0) * HD_ + dd) = v0;
                const int m1 = m0 + 8;
                const int bb1 = m1 >> 11, ss1 = m1 & 2047;
                *(float2*)(out + (((size_t)bb1 * NH_ + hh) * SQ_ + ss1) * HD_ + dd) = v1;
            } else {
                *(float2*)(out + (size_t)m0 * H_ + n) = v0;
                *(float2*)(out + (size_t)(m0 + 8) * H_ + n) = v1;
            }
        }
    }
}

// ===========================================================================
// Flash attention (fp32) — unchanged (passing, ~980us)
// ===========================================================================
#define ATTN_SMEM_FLOATS (64 * 132 + 64 * 132 + 128 * 68 + 128 * 132)
#define ATTN_SMEM_BYTES  (ATTN_SMEM_FLOATS * 4)

__global__ __launch_bounds__(256, 1)
void attn_kernel(const float* __restrict__ Q, const float* __restrict__ Kin,
                 const float* __restrict__ Vin, const float* __restrict__ mask,
                 float* __restrict__ ctx)
{
    extern __shared__ float sm[];
    float* Qs = sm;                     // [64 d][132]
    float* Ks = sm + 64 * 132;          // [64 d][132]
    float* Vs = sm + 2 * 64 * 132;      // [128 j][68]
    float* Ps = Vs + 128 * 68;          // [128 r][132]

    const int tid = threadIdx.x;
    const int tx = tid & 15, ty = tid >> 4;
    const int q0 = blockIdx.x << 7;
    const int h  = blockIdx.y;
    const int b  = blockIdx.z;

    const float* Qp = Q   + ((size_t)(b * NH_ + h) * SQ_ + q0) * HD_;
    const float* Kp = Kin + (size_t)(b * NH_ + h) * SKV_ * HD_;
    const float* Vp = Vin + (size_t)(b * NH_ + h) * SKV_ * HD_;
    const float* Mp = mask + ((size_t)b * SQ_ + q0) * SKV_;

    for (int idx = tid; idx < 128 * 16; idx += 256) {
        const int r = idx >> 4;
        const int d = (idx & 15) << 2;
        float4 v = *(const float4*)(Qp + r * HD_ + d);
        Qs[(d + 0) * 132 + r] = v.x * 0.125f;
        Qs[(d + 1) * 132 + r] = v.y * 0.125f;
        Qs[(d + 2) * 132 + r] = v.z * 0.125f;
        Qs[(d + 3) * 132 + r] = v.w * 0.125f;
    }

    float m_i[8], l_i[8], o[8][4];
#pragma unroll
    for (int i = 0; i < 8; i++) {
        m_i[i] = -1e30f;
        l_i[i] = 0.f;
        o[i][0] = o[i][1] = o[i][2] = o[i][3] = 0.f;
    }

    for (int t = 0; t < SKV_ / 128; t++) {
        __syncthreads();
        const float* Kt = Kp + (size_t)(t << 7) * HD_;
        const float* Vt = Vp + (size_t)(t << 7) * HD_;
        for (int idx = tid; idx < 128 * 16; idx += 256) {
            const int r = idx >> 4;
            const int d = (idx & 15) << 2;
            float4 v = *(const float4*)(Kt + r * HD_ + d);
            Ks[(d + 0) * 132 + r] = v.x;
            Ks[(d + 1) * 132 + r] = v.y;
            Ks[(d + 2) * 132 + r] = v.z;
            Ks[(d + 3) * 132 + r] = v.w;
            *(float4*)(Vs + r * 68 + d) = *(const float4*)(Vt + r * HD_ + d);
        }
        __syncthreads();

        float s[8][8];
#pragma unroll
        for (int i = 0; i < 8; i++)
#pragma unroll
            for (int j = 0; j < 8; j++) s[i][j] = 0.f;

#pragma unroll 4
        for (int d = 0; d < 64; d++) {
            float a[8], kb[8];
            *(float4*)&a[0]  = *(const float4*)&Qs[d * 132 + ty * 8];
            *(float4*)&a[4]  = *(const float4*)&Qs[d * 132 + ty * 8 + 4];
            *(float4*)&kb[0] = *(const float4*)&Ks[d * 132 + tx * 8];
            *(float4*)&kb[4] = *(const float4*)&Ks[d * 132 + tx * 8 + 4];
#pragma unroll
            for (int i = 0; i < 8; i++)
#pragma unroll
                for (int j = 0; j < 8; j++)
                    s[i][j] = fmaf(a[i], kb[j], s[i][j]);
        }

#pragma unroll
        for (int i = 0; i < 8; i++) {
            const float* mrow = Mp + (size_t)(ty * 8 + i) * SKV_ + (t << 7) + tx * 8;
            float4 m0 = *(const float4*)mrow;
            float4 m1 = *(const float4*)(mrow + 4);
            s[i][0] += (m0.x - 1.f) * 10000.f;
            s[i][1] += (m0.y - 1.f) * 10000.f;
            s[i][2] += (m0.z - 1.f) * 10000.f;
            s[i][3] += (m0.w - 1.f) * 10000.f;
            s[i][4] += (m1.x - 1.f) * 10000.f;
            s[i][5] += (m1.y - 1.f) * 10000.f;
            s[i][6] += (m1.z - 1.f) * 10000.f;
            s[i][7] += (m1.w - 1.f) * 10000.f;

            float mx = s[i][0];
#pragma unroll
            for (int j = 1; j < 8; j++) mx = fmaxf(mx, s[i][j]);
            mx = fmaxf(mx, __shfl_xor_sync(0xffffffffu, mx, 1));
            mx = fmaxf(mx, __shfl_xor_sync(0xffffffffu, mx, 2));
            mx = fmaxf(mx, __shfl_xor_sync(0xffffffffu, mx, 4));
            mx = fmaxf(mx, __shfl_xor_sync(0xffffffffu, mx, 8));

            const float newm = fmaxf(m_i[i], mx);
            const float alpha = __expf(m_i[i] - newm);
            m_i[i] = newm;

            float rs = 0.f;
#pragma unroll
            for (int j = 0; j < 8; j++) {
                s[i][j] = __expf(s[i][j] - newm);
                rs += s[i][j];
            }
            rs += __shfl_xor_sync(0xffffffffu, rs, 1);
            rs += __shfl_xor_sync(0xffffffffu, rs, 2);
            rs += __shfl_xor_sync(0xffffffffu, rs, 4);
            rs += __shfl_xor_sync(0xffffffffu, rs, 8);

            l_i[i] = l_i[i] * alpha + rs;
            o[i][0] *= alpha; o[i][1] *= alpha; o[i][2] *= alpha; o[i][3] *= alpha;

            float4 p0 = make_float4(s[i][0], s[i][1], s[i][2], s[i][3]);
            float4 p1 = make_float4(s[i][4], s[i][5], s[i][6], s[i][7]);
            *(float4*)&Ps[(ty * 8 + i) * 132 + tx * 8]     = p0;
            *(float4*)&Ps[(ty * 8 + i) * 132 + tx * 8 + 4] = p1;
        }
        __syncthreads();

#pragma unroll 2
        for (int j = 0; j < 128; j++) {
            const float4 vv = *(const float4*)&Vs[j * 68 + tx * 4];
#pragma unroll
            for (int i = 0; i < 8; i++) {
                const float p = Ps[(ty * 8 + i) * 132 + j];
                o[i][0] = fmaf(p, vv.x, o[i][0]);
                o[i][1] = fmaf(p, vv.y, o[i][1]);
                o[i][2] = fmaf(p, vv.z, o[i][2]);
                o[i][3] = fmaf(p, vv.w, o[i][3]);
            }
        }
    }

#pragma unroll
    for (int i = 0; i < 8; i++) {
        const float inv = 1.f / l_i[i];
        float4 r = make_float4(o[i][0] * inv, o[i][1] * inv, o[i][2] * inv, o[i][3] * inv);
        *(float4*)(ctx + ((size_t)b * SQ_ + q0 + ty * 8 + i) * H_ + h * HD_ + tx * 4) = r;
    }
}

// ===========================================================================
extern "C" void kernel_launch(void* const* d_in, const int* in_sizes, int n_in,
                              void* d_out, int out_size)
{
    (void)in_sizes; (void)n_in; (void)out_size;
    const float* xq  = (const float*)d_in[0];
    const float* xkv = (const float*)d_in[1];
    const float* msk = (const float*)d_in[2];
    const float* Wq  = (const float*)d_in[3];
    const float* bq  = (const float*)d_in[4];
    const float* Wk  = (const float*)d_in[5];
    const float* Wv  = (const float*)d_in[6];
    const float* bv  = (const float*)d_in[7];
    const float* Wo  = (const float*)d_in[8];
    const float* bo  = (const float*)d_in[9];
    float* out = (float*)d_out;

    float *q, *k, *v, *ctx;
    cudaGetSymbolAddress((void**)&q,   g_q);
    cudaGetSymbolAddress((void**)&k,   g_k);
    cudaGetSymbolAddress((void**)&v,   g_v);
    cudaGetSymbolAddress((void**)&ctx, g_ctx);

    __nv_bfloat16 *xqh, *xql, *xkvh, *xkvl, *wqh, *wql, *wkh, *wkl, *wvh, *wvl, *woh, *wol, *cth, *ctl;
    cudaGetSymbolAddress((void**)&xqh,  g_xq_h);  cudaGetSymbolAddress((void**)&xql,  g_xq_l);
    cudaGetSymbolAddress((void**)&xkvh, g_xkv_h); cudaGetSymbolAddress((void**)&xkvl, g_xkv_l);
    cudaGetSymbolAddress((void**)&wqh,  g_wq_h);  cudaGetSymbolAddress((void**)&wql,  g_wq_l);
    cudaGetSymbolAddress((void**)&wkh,  g_wk_h);  cudaGetSymbolAddress((void**)&wkl,  g_wk_l);
    cudaGetSymbolAddress((void**)&wvh,  g_wv_h);  cudaGetSymbolAddress((void**)&wvl,  g_wv_l);
    cudaGetSymbolAddress((void**)&woh,  g_wo_h);  cudaGetSymbolAddress((void**)&wol,  g_wo_l);
    cudaGetSymbolAddress((void**)&cth,  g_ctx_h); cudaGetSymbolAddress((void**)&ctl,  g_ctx_l);

    cudaFuncSetAttribute(proj_mma, cudaFuncAttributeMaxDynamicSharedMemorySize, PROJ_SMEM);
    cudaFuncSetAttribute(attn_kernel, cudaFuncAttributeMaxDynamicSharedMemorySize, ATTN_SMEM_BYTES);

    const int nX = M_ * K_;   // 4M
    const int nW = H_ * K_;   // 1M
    split_kernel<<<nX / 4 / 256, 256>>>(xq,  xqh,  xql,  nX);
    split_kernel<<<nX / 4 / 256, 256>>>(xkv, xkvh, xkvl, nX);
    split_kernel<<<nW / 4 / 256, 256>>>(Wq,  wqh,  wql,  nW);
    split_kernel<<<nW / 4 / 256, 256>>>(Wk,  wkh,  wkl,  nW);
    split_kernel<<<nW / 4 / 256, 256>>>(Wv,  wvh,  wvl,  nW);
    split_kernel<<<nW / 4 / 256, 256>>>(Wo,  woh,  wol,  nW);

    dim3 pg(H_ / 128, M_ / 128);  // (8, 32)
    proj_mma<<<pg, 256, PROJ_SMEM>>>(xqh,  xql,  wqh, wql, bq,      q,   1);
    proj_mma<<<pg, 256, PROJ_SMEM>>>(xkvh, xkvl, wkh, wkl, nullptr, k,   1);
    proj_mma<<<pg, 256, PROJ_SMEM>>>(xkvh, xkvl, wvh, wvl, bv,      v,   1);

    attn_kernel<<<dim3(SQ_ / 128, NH_, B_), 256, ATTN_SMEM_BYTES>>>(q, k, v, msk, ctx);

    split_kernel<<<nX / 4 / 256, 256>>>(ctx, cth, ctl, nX);
    proj_mma<<<pg, 256, PROJ_SMEM>>>(cth, ctl, woh, wol, bo, out, 0);
}

// round 15
// speedup vs baseline: 2.0269x; 1.7002x over previous
#include <cuda_runtime.h>
#include <cuda_bf16.h>
#include <cstdint>

#define B_   2
#define SQ_  2048
#define SKV_ 2048
#define H_   1024
#define NH_  16
#define HD_  64
#define K_   1024
#define M_   4096

#define L2E_F     1.4426950408889634f
#define QSCALE_F  (0.125f * L2E_F)
#define MC_F      (10000.0f * L2E_F)

// ===========================================================================
// Helpers
// ===========================================================================
__device__ __forceinline__ uint32_t smem_to_u32(const void* p) {
    uint32_t a;
    asm("{ .reg .u64 t; cvta.to.shared.u64 t, %1; cvt.u32.u64 %0, t; }"
        : "=r"(a) : "l"(p));
    return a;
}
__device__ __forceinline__ void ldsm4(uint32_t* r, uint32_t addr) {
    asm volatile("ldmatrix.sync.aligned.m8n8.x4.shared.b16 {%0,%1,%2,%3}, [%4];"
                 : "=r"(r[0]), "=r"(r[1]), "=r"(r[2]), "=r"(r[3]) : "r"(addr));
}
__device__ __forceinline__ void ldsm4t(uint32_t* r, uint32_t addr) {
    asm volatile("ldmatrix.sync.aligned.m8n8.x4.trans.shared.b16 {%0,%1,%2,%3}, [%4];"
                 : "=r"(r[0]), "=r"(r[1]), "=r"(r[2]), "=r"(r[3]) : "r"(addr));
}
__device__ __forceinline__ void mma16816(float* d, const uint32_t* a, const uint32_t* b) {
    asm volatile("mma.sync.aligned.m16n8k16.row.col.f32.bf16.bf16.f32 "
                 "{%0,%1,%2,%3}, {%4,%5,%6,%7}, {%8,%9}, {%0,%1,%2,%3};"
                 : "+f"(d[0]), "+f"(d[1]), "+f"(d[2]), "+f"(d[3])
                 : "r"(a[0]), "r"(a[1]), "r"(a[2]), "r"(a[3]), "r"(b[0]), "r"(b[1]));
}
// pack two fp32 -> bf16x2 (lo = first arg, hi = second)
__device__ __forceinline__ uint32_t packbf(float lo, float hi) {
    uint32_t d;
    asm("cvt.rn.bf16x2.f32 %0, %1, %2;" : "=r"(d) : "f"(hi), "f"(lo));
    return d;
}
__device__ __forceinline__ float lowbf(uint32_t p)  { return __int_as_float(p << 16); }
__device__ __forceinline__ float highbf(uint32_t p) { return __int_as_float(p & 0xffff0000u); }

// fast 2^y on FMA/ALU pipes (no MUFU, no CVT). Valid for y <= ~30.
__device__ __forceinline__ float exp2p(float y) {
    y = fmaxf(y, -125.0f);
    float t = y + 12582912.0f;          // 1.5*2^23: RN rounds y to integer n
    int   i = __float_as_int(t);        // i = 0x4B400000 + n
    float f = y - (t - 12582912.0f);    // f in [-0.5, 0.5]
    float p = 0.0013333558f;
    p = fmaf(p, f, 0.0096181291f);
    p = fmaf(p, f, 0.0555041087f);
    p = fmaf(p, f, 0.2402265069f);
    p = fmaf(p, f, 0.6931471806f);
    p = fmaf(p, f, 1.0f);
    return p * __int_as_float((i << 23) + 0x3f800000); // * 2^n
}
#define SMEM_SWIZZLE_128B(off) ((off) ^ (((off) >> 3) & 0x70))

// ===========================================================================
// Scratch
// ===========================================================================
__device__ float g_ctx[(size_t)B_ * SQ_ * H_];

__device__ __nv_bfloat16 g_qh[(size_t)B_ * NH_ * SQ_ * HD_],  g_ql[(size_t)B_ * NH_ * SQ_ * HD_];
__device__ __nv_bfloat16 g_kh[(size_t)B_ * NH_ * SKV_ * HD_], g_kl[(size_t)B_ * NH_ * SKV_ * HD_];
__device__ __nv_bfloat16 g_vh[(size_t)B_ * NH_ * SKV_ * HD_], g_vl[(size_t)B_ * NH_ * SKV_ * HD_];

__device__ __nv_bfloat16 g_xq_h[(size_t)M_ * K_],  g_xq_l[(size_t)M_ * K_];
__device__ __nv_bfloat16 g_xkv_h[(size_t)M_ * K_], g_xkv_l[(size_t)M_ * K_];
__device__ __nv_bfloat16 g_wq_h[(size_t)H_ * K_],  g_wq_l[(size_t)H_ * K_];
__device__ __nv_bfloat16 g_wk_h[(size_t)H_ * K_],  g_wk_l[(size_t)H_ * K_];
__device__ __nv_bfloat16 g_wv_h[(size_t)H_ * K_],  g_wv_l[(size_t)H_ * K_];
__device__ __nv_bfloat16 g_wo_h[(size_t)H_ * K_],  g_wo_l[(size_t)H_ * K_];
__device__ __nv_bfloat16 g_ctx_h[(size_t)M_ * K_], g_ctx_l[(size_t)M_ * K_];

// ===========================================================================
// fp32 -> (bf16 hi, bf16 lo) split kernel
// ===========================================================================
__global__ __launch_bounds__(256)
void split_kernel(const float* __restrict__ x, __nv_bfloat16* __restrict__ hi,
                  __nv_bfloat16* __restrict__ lo, int n)
{
    int i = (blockIdx.x * 256 + threadIdx.x) * 4;
    if (i >= n) return;
    float4 v = *(const float4*)(x + i);
    float f[4] = {v.x, v.y, v.z, v.w};
    unsigned short hs[4], ls[4];
#pragma unroll
    for (int j = 0; j < 4; j++) {
        __nv_bfloat16 h = __float2bfloat16(f[j]);
        __nv_bfloat16 l = __float2bfloat16(f[j] - __bfloat162float(h));
        hs[j] = *(unsigned short*)&h;
        ls[j] = *(unsigned short*)&l;
    }
    *(ushort4*)((unsigned short*)hi + i) = make_ushort4(hs[0], hs[1], hs[2], hs[3]);
    *(ushort4*)((unsigned short*)lo + i) = make_ushort4(ls[0], ls[1], ls[2], ls[3]);
}

// ===========================================================================
// mma.sync projection GEMM (validated R6).
// mode 0: fp32 flat [M,H] to outF.   mode 1: split-head bf16 hi/lo (scaled).
// ===========================================================================
#define OFF_AH 0
#define OFF_AL (OFF_AH + 16384)
#define OFF_BH (OFF_AL + 16384)
#define OFF_BL (OFF_BH + 16384)
#define PROJ_SMEM (OFF_BL + 16384)

__global__ __launch_bounds__(256, 1)
void proj_mma(const __nv_bfloat16* __restrict__ Ah, const __nv_bfloat16* __restrict__ Al,
              const __nv_bfloat16* __restrict__ Bh, const __nv_bfloat16* __restrict__ Bl,
              const float* __restrict__ bias, float* __restrict__ outF,
              __nv_bfloat16* __restrict__ outH, __nv_bfloat16* __restrict__ outL,
              float scale, int mode)
{
    extern __shared__ char smem[];
    const uint32_t sb = smem_to_u32(smem);
    const int tid  = threadIdx.x;
    const int wid  = tid >> 5, lane = tid & 31;
    const int bn = blockIdx.x * 128;
    const int bm = blockIdx.y * 128;
    const int wm = (wid >> 2) * 64;
    const int wn = (wid & 3) * 32;

    float acc[4][4][4];
#pragma unroll
    for (int i = 0; i < 4; i++)
#pragma unroll
        for (int j = 0; j < 4; j++)
#pragma unroll
            for (int r = 0; r < 4; r++) acc[i][j][r] = 0.f;

    const int a_rl  = (lane & 7) + ((lane >> 3) & 1) * 8;
    const int a_kc8 = (lane >> 4) * 8;
    const int b_rl  = (lane & 7) + (lane >> 4) * 8;
    const int b_kc8 = ((lane >> 3) & 1) * 8;

    uint32_t aRow[4], aXor[4];
#pragma unroll
    for (int i = 0; i < 4; i++) {
        const int r = wm + i * 16 + a_rl;
        aRow[i] = (uint32_t)r * 128u;
        aXor[i] = (uint32_t)((r & 7) << 4);
    }
    uint32_t bRow[2], bXor[2];
#pragma unroll
    for (int jp = 0; jp < 2; jp++) {
        const int r = wn + jp * 16 + b_rl;
        bRow[jp] = (uint32_t)r * 128u;
        bXor[jp] = (uint32_t)((r & 7) << 4);
    }

    for (int step = 0; step < 16; step++) {
        const int k0g = step * 64;
        for (int idx = tid; idx < 1024; idx += 256) {
            const int r  = idx >> 3;
            const int cu = idx & 7;
            const uint32_t so = SMEM_SWIZZLE_128B((uint32_t)(r * 128 + cu * 16));
            const size_t ga = (size_t)(bm + r) * K_ + k0g + cu * 8;
            const size_t gb = (size_t)(bn + r) * K_ + k0g + cu * 8;
            *(uint4*)(smem + OFF_AH + so) = *(const uint4*)(Ah + ga);
            *(uint4*)(smem + OFF_AL + so) = *(const uint4*)(Al + ga);
            *(uint4*)(smem + OFF_BH + so) = *(const uint4*)(Bh + gb);
            *(uint4*)(smem + OFF_BL + so) = *(const uint4*)(Bl + gb);
        }
        __syncthreads();

#pragma unroll
        for (int kk = 0; kk < 4; kk++) {
            const uint32_t ka = (uint32_t)(2 * (kk * 16 + a_kc8));
            const uint32_t kb = (uint32_t)(2 * (kk * 16 + b_kc8));

            uint32_t ah[4][4], al[4][4];
#pragma unroll
            for (int i = 0; i < 4; i++) {
                const uint32_t off = aRow[i] + (ka ^ aXor[i]);
                ldsm4(ah[i], sb + OFF_AH + off);
                ldsm4(al[i], sb + OFF_AL + off);
            }
            uint32_t bh[2][4], bl[2][4];
#pragma unroll
            for (int jp = 0; jp < 2; jp++) {
                const uint32_t off = bRow[jp] + (kb ^ bXor[jp]);
                ldsm4(bh[jp], sb + OFF_BH + off);
                ldsm4(bl[jp], sb + OFF_BL + off);
            }

#pragma unroll
            for (int i = 0; i < 4; i++)
#pragma unroll
                for (int j = 0; j < 4; j++) {
                    const uint32_t* fbh = &bh[j >> 1][(j & 1) * 2];
                    const uint32_t* fbl = &bl[j >> 1][(j & 1) * 2];
                    mma16816(acc[i][j], ah[i], fbh);
                    mma16816(acc[i][j], ah[i], fbl);
                    mma16816(acc[i][j], al[i], fbh);
                }
        }
        __syncthreads();
    }

    const int mt = lane >> 2;
    const int nt = (lane & 3) * 2;
#pragma unroll
    for (int i = 0; i < 4; i++) {
        const int m0 = bm + wm + i * 16 + mt;
#pragma unroll
        for (int j = 0; j < 4; j++) {
            const int n = bn + wn + j * 8 + nt;
            float b0 = 0.f, b1 = 0.f;
            if (bias) { b0 = bias[n]; b1 = bias[n + 1]; }
            float f0 = acc[i][j][0] + b0, f1 = acc[i][j][1] + b1;
            float f2 = acc[i][j][2] + b0, f3 = acc[i][j][3] + b1;
            if (mode == 0) {
                *(float2*)(outF + (size_t)m0 * H_ + n) = make_float2(f0, f1);
                *(float2*)(outF + (size_t)(m0 + 8) * H_ + n) = make_float2(f2, f3);
            } else {
                f0 *= scale; f1 *= scale; f2 *= scale; f3 *= scale;
                const int hh = n >> 6, dd = n & 63;
                const int bb0 = m0 >> 11, ss0 = m0 & 2047;
                const int m1 = m0 + 8;
                const int bb1 = m1 >> 11, ss1 = m1 & 2047;
                const size_t i0 = (((size_t)bb0 * NH_ + hh) * SQ_ + ss0) * HD_ + dd;
                const size_t i1 = (((size_t)bb1 * NH_ + hh) * SQ_ + ss1) * HD_ + dd;
                uint32_t p01 = packbf(f0, f1);
                uint32_t p23 = packbf(f2, f3);
                uint32_t r01 = packbf(f0 - lowbf(p01), f1 - highbf(p01));
                uint32_t r23 = packbf(f2 - lowbf(p23), f3 - highbf(p23));
                *(uint32_t*)(outH + i0) = p01;
                *(uint32_t*)(outL + i0) = r01;
                *(uint32_t*)(outH + i1) = p23;
                *(uint32_t*)(outL + i1) = r23;
            }
        }
    }
}

// ===========================================================================
// Flash attention via mma.sync, split-bf16 everywhere, poly exp2 (no MUFU).
// Grid (NH, SQ/128, B), 256 threads, warp w owns q-rows 16w..16w+15.
// ===========================================================================
#define AT_QH 0
#define AT_QL (AT_QH + 16384)
#define AT_KH (AT_QL + 16384)
#define AT_KL (AT_KH + 16384)
#define AT_VH (AT_KL + 16384)
#define AT_VL (AT_VH + 16384)
#define AT_SMEM (AT_VL + 16384)   /* 98304 bytes */

__global__ __launch_bounds__(256, 1)
void attn_mma(const __nv_bfloat16* __restrict__ Qh_, const __nv_bfloat16* __restrict__ Ql_,
              const __nv_bfloat16* __restrict__ Kh_, const __nv_bfloat16* __restrict__ Kl_,
              const __nv_bfloat16* __restrict__ Vh_, const __nv_bfloat16* __restrict__ Vl_,
              const float* __restrict__ mask, float* __restrict__ ctx)
{
    extern __shared__ char smem[];
    const uint32_t sb = smem_to_u32(smem);
    const int tid = threadIdx.x, wid = tid >> 5, lane = tid & 31;
    const int h = blockIdx.x, q0 = blockIdx.y << 7, b = blockIdx.z;
    const size_t bh = (size_t)b * NH_ + h;

    const __nv_bfloat16* Qhp = Qh_ + (bh * SQ_ + q0) * HD_;
    const __nv_bfloat16* Qlp = Ql_ + (bh * SQ_ + q0) * HD_;
    const __nv_bfloat16* Khp = Kh_ + bh * SKV_ * HD_;
    const __nv_bfloat16* Klp = Kl_ + bh * SKV_ * HD_;
    const __nv_bfloat16* Vhp = Vh_ + bh * SKV_ * HD_;
    const __nv_bfloat16* Vlp = Vl_ + bh * SKV_ * HD_;

    // load Q tiles (swizzled)
    for (int idx = tid; idx < 1024; idx += 256) {
        const int r = idx >> 3, cu = idx & 7;
        const uint32_t so = SMEM_SWIZZLE_128B((uint32_t)(r * 128 + cu * 16));
        const int g = r * HD_ + cu * 8;
        *(uint4*)(smem + AT_QH + so) = *(const uint4*)(Qhp + g);
        *(uint4*)(smem + AT_QL + so) = *(const uint4*)(Qlp + g);
    }
    __syncthreads();

    const uint32_t sxor = (uint32_t)((lane & 7) << 4);

    // Q fragments (resident for whole kernel)
    const int a_rl = (lane & 7) + ((lane >> 3) & 1) * 8;
    const int a_k  = (lane >> 4) * 8;
    uint32_t qh[4][4], ql[4][4];
#pragma unroll
    for (int c = 0; c < 4; c++) {
        const uint32_t off = (uint32_t)(wid * 16 + a_rl) * 128u
                           + (((uint32_t)((c * 16 + a_k) * 2)) ^ sxor);
        ldsm4(qh[c], sb + AT_QH + off);
        ldsm4(ql[c], sb + AT_QL + off);
    }

    const int r0 = wid * 16 + (lane >> 2);          // local q row (and r0+8)
    const float* mp0 = mask + ((size_t)b * SQ_ + q0 + r0) * SKV_ + (lane & 3) * 2;
    const float* mp1 = mp0 + 8 * SKV_;

    float o[8][4];
#pragma unroll
    for (int j = 0; j < 8; j++) { o[j][0] = o[j][1] = o[j][2] = o[j][3] = 0.f; }
    float m0 = -1e30f, m1 = -1e30f, l0 = 0.f, l1 = 0.f;

    const int b_rl = (lane & 7) + (lane >> 4) * 8;
    const int b_k  = ((lane >> 3) & 1) * 8;
    const int v_r  = lane & 15;
    const int v_c  = (lane >> 4) * 16;

    for (int t = 0; t < 16; t++) {
        __syncthreads();
        const __nv_bfloat16* kh_t = Khp + (size_t)(t << 7) * HD_;
        const __nv_bfloat16* kl_t = Klp + (size_t)(t << 7) * HD_;
        const __nv_bfloat16* vh_t = Vhp + (size_t)(t << 7) * HD_;
        const __nv_bfloat16* vl_t = Vlp + (size_t)(t << 7) * HD_;
        for (int idx = tid; idx < 1024; idx += 256) {
            const int r = idx >> 3, cu = idx & 7;
            const uint32_t so = SMEM_SWIZZLE_128B((uint32_t)(r * 128 + cu * 16));
            const int g = r * HD_ + cu * 8;
            *(uint4*)(smem + AT_KH + so) = *(const uint4*)(kh_t + g);
            *(uint4*)(smem + AT_KL + so) = *(const uint4*)(kl_t + g);
            *(uint4*)(smem + AT_VH + so) = *(const uint4*)(vh_t + g);
            *(uint4*)(smem + AT_VL + so) = *(const uint4*)(vl_t + g);
        }
        __syncthreads();

        // ---- S = Q K^T (split-bf16, base-2 units) ----
        float s[16][4];
#pragma unroll
        for (int j = 0; j < 16; j++) { s[j][0] = s[j][1] = s[j][2] = s[j][3] = 0.f; }

#pragma unroll
        for (int c = 0; c < 4; c++) {
            const uint32_t kc = ((uint32_t)((c * 16 + b_k) * 2)) ^ sxor;
#pragma unroll
            for (int jp = 0; jp < 8; jp++) {
                uint32_t kh[4], kl[4];
                const uint32_t off = (uint32_t)(jp * 16 + b_rl) * 128u + kc;
                ldsm4(kh, sb + AT_KH + off);
                ldsm4(kl, sb + AT_KL + off);
                mma16816(s[2 * jp],     qh[c], kh);
                mma16816(s[2 * jp],     qh[c], kl);
                mma16816(s[2 * jp],     ql[c], kh);
                mma16816(s[2 * jp + 1], qh[c], kh + 2);
                mma16816(s[2 * jp + 1], qh[c], kl + 2);
                mma16816(s[2 * jp + 1], ql[c], kh + 2);
            }
        }

        // ---- mask (additive, pre-scaled to base-2) ----
        const float* q0m = mp0 + (t << 7);
        const float* q1m = mp1 + (t << 7);
#pragma unroll
        for (int j = 0; j < 16; j++) {
            float2 u0 = *(const float2*)(q0m + j * 8);
            float2 u1 = *(const float2*)(q1m + j * 8);
            s[j][0] = fmaf(u0.x - 1.f, MC_F, s[j][0]);
            s[j][1] = fmaf(u0.y - 1.f, MC_F, s[j][1]);
            s[j][2] = fmaf(u1.x - 1.f, MC_F, s[j][2]);
            s[j][3] = fmaf(u1.y - 1.f, MC_F, s[j][3]);
        }

        // ---- online softmax (rows r0 and r0+8; quad = 4 lanes per row) ----
        float mx0 = s[0][0], mx1 = s[0][2];
#pragma unroll
        for (int j = 0; j < 16; j++) {
            mx0 = fmaxf(mx0, fmaxf(s[j][0], s[j][1]));
            mx1 = fmaxf(mx1, fmaxf(s[j][2], s[j][3]));
        }
        mx0 = fmaxf(mx0, __shfl_xor_sync(0xffffffffu, mx0, 1));
        mx0 = fmaxf(mx0, __shfl_xor_sync(0xffffffffu, mx0, 2));
        mx1 = fmaxf(mx1, __shfl_xor_sync(0xffffffffu, mx1, 1));
        mx1 = fmaxf(mx1, __shfl_xor_sync(0xffffffffu, mx1, 2));

        const float nm0 = fmaxf(m0, mx0), nm1 = fmaxf(m1, mx1);
        const float a0 = exp2p(m0 - nm0), a1 = exp2p(m1 - nm1);
        m0 = nm0; m1 = nm1;

        float rs0 = 0.f, rs1 = 0.f;
#pragma unroll
        for (int j = 0; j < 16; j++) {
            s[j][0] = exp2p(s[j][0] - m0);
            s[j][1] = exp2p(s[j][1] - m0);
            s[j][2] = exp2p(s[j][2] - m1);
            s[j][3] = exp2p(s[j][3] - m1);
            rs0 += s[j][0] + s[j][1];
            rs1 += s[j][2] + s[j][3];
        }
        rs0 += __shfl_xor_sync(0xffffffffu, rs0, 1);
        rs0 += __shfl_xor_sync(0xffffffffu, rs0, 2);
        rs1 += __shfl_xor_sync(0xffffffffu, rs1, 1);
        rs1 += __shfl_xor_sync(0xffffffffu, rs1, 2);
        l0 = l0 * a0 + rs0;
        l1 = l1 * a1 + rs1;

#pragma unroll
        for (int j = 0; j < 8; j++) {
            o[j][0] *= a0; o[j][1] *= a0;
            o[j][2] *= a1; o[j][3] *= a1;
        }

        // ---- O += P V (split P, split V; P frags straight from S regs) ----
#pragma unroll
        for (int c = 0; c < 8; c++) {
            uint32_t ph[4], pl[4];
            ph[0] = packbf(s[2 * c][0],     s[2 * c][1]);
            ph[1] = packbf(s[2 * c][2],     s[2 * c][3]);
            ph[2] = packbf(s[2 * c + 1][0], s[2 * c + 1][1]);
            ph[3] = packbf(s[2 * c + 1][2], s[2 * c + 1][3]);
            pl[0] = packbf(s[2 * c][0] - lowbf(ph[0]),     s[2 * c][1] - highbf(ph[0]));
            pl[1] = packbf(s[2 * c][2] - lowbf(ph[1]),     s[2 * c][3] - highbf(ph[1]));
            pl[2] = packbf(s[2 * c + 1][0] - lowbf(ph[2]), s[2 * c + 1][1] - highbf(ph[2]));
            pl[3] = packbf(s[2 * c + 1][2] - lowbf(ph[3]), s[2 * c + 1][3] - highbf(ph[3]));

            const uint32_t vrow = (uint32_t)(c * 16 + v_r) * 128u;
#pragma unroll
            for (int dg = 0; dg < 4; dg++) {
                uint32_t vh[4], vl[4];
                const uint32_t off = vrow + (((uint32_t)(v_c + dg * 32)) ^ sxor);
                ldsm4t(vh, sb + AT_VH + off);
                ldsm4t(vl, sb + AT_VL + off);
                mma16816(o[2 * dg],     ph, vh);
                mma16816(o[2 * dg],     ph, vl);
                mma16816(o[2 * dg],     pl, vh);
                mma16816(o[2 * dg + 1], ph, vh + 2);
                mma16816(o[2 * dg + 1], ph, vl + 2);
                mma16816(o[2 * dg + 1], pl, vh + 2);
            }
        }
    }

    // ---- epilogue: ctx[b][q][h*64+d] ----
    const float i0 = 1.f / l0, i1 = 1.f / l1;
    float* c0 = ctx + ((size_t)b * SQ_ + q0 + r0) * H_ + h * HD_ + (lane & 3) * 2;
    float* c1 = c0 + 8 * H_;
#pragma unroll
    for (int j = 0; j < 8; j++) {
        *(float2*)(c0 + j * 8) = make_float2(o[j][0] * i0, o[j][1] * i0);
        *(float2*)(c1 + j * 8) = make_float2(o[j][2] * i1, o[j][3] * i1);
    }
}

// ===========================================================================
extern "C" void kernel_launch(void* const* d_in, const int* in_sizes, int n_in,
                              void* d_out, int out_size)
{
    (void)in_sizes; (void)n_in; (void)out_size;
    const float* xq  = (const float*)d_in[0];
    const float* xkv = (const float*)d_in[1];
    const float* msk = (const float*)d_in[2];
    const float* Wq  = (const float*)d_in[3];
    const float* bq  = (const float*)d_in[4];
    const float* Wk  = (const float*)d_in[5];
    const float* Wv  = (const float*)d_in[6];
    const float* bv  = (const float*)d_in[7];
    const float* Wo  = (const float*)d_in[8];
    const float* bo  = (const float*)d_in[9];
    float* out = (float*)d_out;

    float* ctx;
    cudaGetSymbolAddress((void**)&ctx, g_ctx);

    __nv_bfloat16 *qh, *ql, *kh, *kl, *vh, *vl;
    cudaGetSymbolAddress((void**)&qh, g_qh); cudaGetSymbolAddress((void**)&ql, g_ql);
    cudaGetSymbolAddress((void**)&kh, g_kh); cudaGetSymbolAddress((void**)&kl, g_kl);
    cudaGetSymbolAddress((void**)&vh, g_vh); cudaGetSymbolAddress((void**)&vl, g_vl);

    __nv_bfloat16 *xqh, *xql, *xkvh, *xkvl, *wqh, *wql, *wkh, *wkl, *wvh, *wvl, *woh, *wol, *cth, *ctl;
    cudaGetSymbolAddress((void**)&xqh,  g_xq_h);  cudaGetSymbolAddress((void**)&xql,  g_xq_l);
    cudaGetSymbolAddress((void**)&xkvh, g_xkv_h); cudaGetSymbolAddress((void**)&xkvl, g_xkv_l);
    cudaGetSymbolAddress((void**)&wqh,  g_wq_h);  cudaGetSymbolAddress((void**)&wql,  g_wq_l);
    cudaGetSymbolAddress((void**)&wkh,  g_wk_h);  cudaGetSymbolAddress((void**)&wkl,  g_wk_l);
    cudaGetSymbolAddress((void**)&wvh,  g_wv_h);  cudaGetSymbolAddress((void**)&wvl,  g_wv_l);
    cudaGetSymbolAddress((void**)&woh,  g_wo_h);  cudaGetSymbolAddress((void**)&wol,  g_wo_l);
    cudaGetSymbolAddress((void**)&cth,  g_ctx_h); cudaGetSymbolAddress((void**)&ctl,  g_ctx_l);

    cudaFuncSetAttribute(proj_mma, cudaFuncAttributeMaxDynamicSharedMemorySize, PROJ_SMEM);
    cudaFuncSetAttribute(attn_mma, cudaFuncAttributeMaxDynamicSharedMemorySize, AT_SMEM);

    const int nX = M_ * K_;
    const int nW = H_ * K_;
    split_kernel<<<nX / 4 / 256, 256>>>(xq,  xqh,  xql,  nX);
    split_kernel<<<nX / 4 / 256, 256>>>(xkv, xkvh, xkvl, nX);
    split_kernel<<<nW / 4 / 256, 256>>>(Wq,  wqh,  wql,  nW);
    split_kernel<<<nW / 4 / 256, 256>>>(Wk,  wkh,  wkl,  nW);
    split_kernel<<<nW / 4 / 256, 256>>>(Wv,  wvh,  wvl,  nW);
    split_kernel<<<nW / 4 / 256, 256>>>(Wo,  woh,  wol,  nW);

    dim3 pg(H_ / 128, M_ / 128);
    proj_mma<<<pg, 256, PROJ_SMEM>>>(xqh,  xql,  wqh, wql, bq,      nullptr, qh, ql, QSCALE_F, 1);
    proj_mma<<<pg, 256, PROJ_SMEM>>>(xkvh, xkvl, wkh, wkl, nullptr, nullptr, kh, kl, 1.0f,     1);
    proj_mma<<<pg, 256, PROJ_SMEM>>>(xkvh, xkvl, wvh, wvl, bv,      nullptr, vh, vl, 1.0f,     1);

    attn_mma<<<dim3(NH_, SQ_ / 128, B_), 256, AT_SMEM>>>(qh, ql, kh, kl, vh, vl, msk, ctx);

    split_kernel<<<nX / 4 / 256, 256>>>(ctx, cth, ctl, nX);
    proj_mma<<<pg, 256, PROJ_SMEM>>>(cth, ctl, woh, wol, bo, out, nullptr, nullptr, 1.0f, 0);
}

// round 17
// speedup vs baseline: 2.6550x; 1.3099x over previous
#include <cuda_runtime.h>
#include <cuda_bf16.h>
#include <cstdint>

#define B_   2
#define SQ_  2048
#define SKV_ 2048
#define H_   1024
#define NH_  16
#define HD_  64
#define K_   1024
#define M_   4096

#define L2E_F     1.4426950408889634f
#define QSCALE_F  (0.125f * L2E_F)
#define MC_F      (10000.0f * L2E_F)

// ===========================================================================
// Helpers
// ===========================================================================
__device__ __forceinline__ uint32_t smem_to_u32(const void* p) {
    uint32_t a;
    asm("{ .reg .u64 t; cvta.to.shared.u64 t, %1; cvt.u32.u64 %0, t; }"
        : "=r"(a) : "l"(p));
    return a;
}
__device__ __forceinline__ void ldsm4(uint32_t* r, uint32_t addr) {
    asm volatile("ldmatrix.sync.aligned.m8n8.x4.shared.b16 {%0,%1,%2,%3}, [%4];"
                 : "=r"(r[0]), "=r"(r[1]), "=r"(r[2]), "=r"(r[3]) : "r"(addr));
}
__device__ __forceinline__ void ldsm4t(uint32_t* r, uint32_t addr) {
    asm volatile("ldmatrix.sync.aligned.m8n8.x4.trans.shared.b16 {%0,%1,%2,%3}, [%4];"
                 : "=r"(r[0]), "=r"(r[1]), "=r"(r[2]), "=r"(r[3]) : "r"(addr));
}
__device__ __forceinline__ void mma16816(float* d, const uint32_t* a, const uint32_t* b) {
    asm volatile("mma.sync.aligned.m16n8k16.row.col.f32.bf16.bf16.f32 "
                 "{%0,%1,%2,%3}, {%4,%5,%6,%7}, {%8,%9}, {%0,%1,%2,%3};"
                 : "+f"(d[0]), "+f"(d[1]), "+f"(d[2]), "+f"(d[3])
                 : "r"(a[0]), "r"(a[1]), "r"(a[2]), "r"(a[3]), "r"(b[0]), "r"(b[1]));
}
__device__ __forceinline__ void cp16(uint32_t saddr, const void* gaddr) {
    asm volatile("cp.async.cg.shared.global [%0], [%1], 16;"
                 :: "r"(saddr), "l"(gaddr) : "memory");
}
// pack two fp32 -> bf16x2 (lo = first arg, hi = second)
__device__ __forceinline__ uint32_t packbf(float lo, float hi) {
    uint32_t d;
    asm("cvt.rn.bf16x2.f32 %0, %1, %2;" : "=r"(d) : "f"(hi), "f"(lo));
    return d;
}
__device__ __forceinline__ float lowbf(uint32_t p)  { return __int_as_float(p << 16); }
__device__ __forceinline__ float highbf(uint32_t p) { return __int_as_float(p & 0xffff0000u); }

// fast 2^y on FMA/ALU pipes (no MUFU, no CVT). Valid for y <= ~30.
__device__ __forceinline__ float exp2p(float y) {
    y = fmaxf(y, -125.0f);
    float t = y + 12582912.0f;          // 1.5*2^23: RN rounds y to integer n
    int   i = __float_as_int(t);        // i = 0x4B400000 + n
    float f = y - (t - 12582912.0f);    // f in [-0.5, 0.5]
    float p = 0.0013333558f;
    p = fmaf(p, f, 0.0096181291f);
    p = fmaf(p, f, 0.0555041087f);
    p = fmaf(p, f, 0.2402265069f);
    p = fmaf(p, f, 0.6931471806f);
    p = fmaf(p, f, 1.0f);
    return p * __int_as_float((i << 23) + 0x3f800000); // * 2^n
}
#define SMEM_SWIZZLE_128B(off) ((off) ^ (((off) >> 3) & 0x70))

// ===========================================================================
// Scratch
// ===========================================================================
__device__ float g_ctx[(size_t)B_ * SQ_ * H_];

__device__ __nv_bfloat16 g_qh[(size_t)B_ * NH_ * SQ_ * HD_],  g_ql[(size_t)B_ * NH_ * SQ_ * HD_];
__device__ __nv_bfloat16 g_kh[(size_t)B_ * NH_ * SKV_ * HD_], g_kl[(size_t)B_ * NH_ * SKV_ * HD_];
__device__ __nv_bfloat16 g_vh[(size_t)B_ * NH_ * SKV_ * HD_], g_vl[(size_t)B_ * NH_ * SKV_ * HD_];

__device__ __nv_bfloat16 g_xq_h[(size_t)M_ * K_],  g_xq_l[(size_t)M_ * K_];
__device__ __nv_bfloat16 g_xkv_h[(size_t)M_ * K_], g_xkv_l[(size_t)M_ * K_];
__device__ __nv_bfloat16 g_wq_h[(size_t)H_ * K_],  g_wq_l[(size_t)H_ * K_];
__device__ __nv_bfloat16 g_wk_h[(size_t)H_ * K_],  g_wk_l[(size_t)H_ * K_];
__device__ __nv_bfloat16 g_wv_h[(size_t)H_ * K_],  g_wv_l[(size_t)H_ * K_];
__device__ __nv_bfloat16 g_wo_h[(size_t)H_ * K_],  g_wo_l[(size_t)H_ * K_];
__device__ __nv_bfloat16 g_ctx_h[(size_t)M_ * K_], g_ctx_l[(size_t)M_ * K_];

// ===========================================================================
// fp32 -> (bf16 hi, bf16 lo) split kernel
// ===========================================================================
__global__ __launch_bounds__(256)
void split_kernel(const float* __restrict__ x, __nv_bfloat16* __restrict__ hi,
                  __nv_bfloat16* __restrict__ lo, int n)
{
    int i = (blockIdx.x * 256 + threadIdx.x) * 4;
    if (i >= n) return;
    float4 v = *(const float4*)(x + i);
    float f[4] = {v.x, v.y, v.z, v.w};
    unsigned short hs[4], ls[4];
#pragma unroll
    for (int j = 0; j < 4; j++) {
        __nv_bfloat16 h = __float2bfloat16(f[j]);
        __nv_bfloat16 l = __float2bfloat16(f[j] - __bfloat162float(h));
        hs[j] = *(unsigned short*)&h;
        ls[j] = *(unsigned short*)&l;
    }
    *(ushort4*)((unsigned short*)hi + i) = make_ushort4(hs[0], hs[1], hs[2], hs[3]);
    *(ushort4*)((unsigned short*)lo + i) = make_ushort4(ls[0], ls[1], ls[2], ls[3]);
}

// ===========================================================================
// mma.sync projection GEMM with 2-stage cp.async double-buffered pipeline.
// mode 0: fp32 flat [M,H] to outF.   mode 1: split-head bf16 hi/lo (scaled).
// ===========================================================================
#define OFF_AH 0
#define OFF_AL (OFF_AH + 16384)
#define OFF_BH (OFF_AL + 16384)
#define OFF_BL (OFF_BH + 16384)
#define PROJ_STAGE 65536
#define PROJ_SMEM (2 * PROJ_STAGE)   /* 131072 bytes */

__global__ __launch_bounds__(256, 1)
void proj_mma(const __nv_bfloat16* __restrict__ Ah, const __nv_bfloat16* __restrict__ Al,
              const __nv_bfloat16* __restrict__ Bh, const __nv_bfloat16* __restrict__ Bl,
              const float* __restrict__ bias, float* __restrict__ outF,
              __nv_bfloat16* __restrict__ outH, __nv_bfloat16* __restrict__ outL,
              float scale, int mode)
{
    extern __shared__ char smem[];
    const uint32_t sb = smem_to_u32(smem);
    const int tid  = threadIdx.x;
    const int wid  = tid >> 5, lane = tid & 31;
    const int bn = blockIdx.x * 128;
    const int bm = blockIdx.y * 128;
    const int wm = (wid >> 2) * 64;
    const int wn = (wid & 3) * 32;

    float acc[4][4][4];
#pragma unroll
    for (int i = 0; i < 4; i++)
#pragma unroll
        for (int j = 0; j < 4; j++)
#pragma unroll
            for (int r = 0; r < 4; r++) acc[i][j][r] = 0.f;

    const int a_rl  = (lane & 7) + ((lane >> 3) & 1) * 8;
    const int a_kc8 = (lane >> 4) * 8;
    const int b_rl  = (lane & 7) + (lane >> 4) * 8;
    const int b_kc8 = ((lane >> 3) & 1) * 8;

    uint32_t aRow[4], aXor[4];
#pragma unroll
    for (int i = 0; i < 4; i++) {
        const int r = wm + i * 16 + a_rl;
        aRow[i] = (uint32_t)r * 128u;
        aXor[i] = (uint32_t)((r & 7) << 4);
    }
    uint32_t bRow[2], bXor[2];
#pragma unroll
    for (int jp = 0; jp < 2; jp++) {
        const int r = wn + jp * 16 + b_rl;
        bRow[jp] = (uint32_t)r * 128u;
        bXor[jp] = (uint32_t)((r & 7) << 4);
    }

    // per-thread cp.async source/dst geometry (4 chunks of 16B per tile)
    auto issue_stage = [&](int step, int buf) {
        const int k0g = step * 64;
        const uint32_t sbase = sb + (uint32_t)buf * PROJ_STAGE;
#pragma unroll
        for (int u = 0; u < 4; u++) {
            const int idx = tid + u * 256;
            const int r  = idx >> 3;
            const int cu = idx & 7;
            const uint32_t so = SMEM_SWIZZLE_128B((uint32_t)(r * 128 + cu * 16));
            const size_t ga = (size_t)(bm + r) * K_ + k0g + cu * 8;
            const size_t gb = (size_t)(bn + r) * K_ + k0g + cu * 8;
            cp16(sbase + OFF_AH + so, Ah + ga);
            cp16(sbase + OFF_AL + so, Al + ga);
            cp16(sbase + OFF_BH + so, Bh + gb);
            cp16(sbase + OFF_BL + so, Bl + gb);
        }
        asm volatile("cp.async.commit_group;" ::: "memory");
    };

    issue_stage(0, 0);

    for (int step = 0; step < 16; step++) {
        const int buf = step & 1;
        if (step + 1 < 16) {
            issue_stage(step + 1, buf ^ 1);
            asm volatile("cp.async.wait_group 1;" ::: "memory");
        } else {
            asm volatile("cp.async.wait_group 0;" ::: "memory");
        }
        __syncthreads();

        const uint32_t sbase = sb + (uint32_t)buf * PROJ_STAGE;
#pragma unroll
        for (int kk = 0; kk < 4; kk++) {
            const uint32_t ka = (uint32_t)(2 * (kk * 16 + a_kc8));
            const uint32_t kb = (uint32_t)(2 * (kk * 16 + b_kc8));

            uint32_t ah[4][4], al[4][4];
#pragma unroll
            for (int i = 0; i < 4; i++) {
                const uint32_t off = aRow[i] + (ka ^ aXor[i]);
                ldsm4(ah[i], sbase + OFF_AH + off);
                ldsm4(al[i], sbase + OFF_AL + off);
            }
            uint32_t bh[2][4], bl[2][4];
#pragma unroll
            for (int jp = 0; jp < 2; jp++) {
                const uint32_t off = bRow[jp] + (kb ^ bXor[jp]);
                ldsm4(bh[jp], sbase + OFF_BH + off);
                ldsm4(bl[jp], sbase + OFF_BL + off);
            }

#pragma unroll
            for (int i = 0; i < 4; i++)
#pragma unroll
                for (int j = 0; j < 4; j++) {
                    const uint32_t* fbh = &bh[j >> 1][(j & 1) * 2];
                    const uint32_t* fbl = &bl[j >> 1][(j & 1) * 2];
                    mma16816(acc[i][j], ah[i], fbh);
                    mma16816(acc[i][j], ah[i], fbl);
                    mma16816(acc[i][j], al[i], fbh);
                }
        }
        __syncthreads();
    }

    const int mt = lane >> 2;
    const int nt = (lane & 3) * 2;
#pragma unroll
    for (int i = 0; i < 4; i++) {
        const int m0 = bm + wm + i * 16 + mt;
#pragma unroll
        for (int j = 0; j < 4; j++) {
            const int n = bn + wn + j * 8 + nt;
            float b0 = 0.f, b1 = 0.f;
            if (bias) { b0 = bias[n]; b1 = bias[n + 1]; }
            float f0 = acc[i][j][0] + b0, f1 = acc[i][j][1] + b1;
            float f2 = acc[i][j][2] + b0, f3 = acc[i][j][3] + b1;
            if (mode == 0) {
                *(float2*)(outF + (size_t)m0 * H_ + n) = make_float2(f0, f1);
                *(float2*)(outF + (size_t)(m0 + 8) * H_ + n) = make_float2(f2, f3);
            } else {
                f0 *= scale; f1 *= scale; f2 *= scale; f3 *= scale;
                const int hh = n >> 6, dd = n & 63;
                const int bb0 = m0 >> 11, ss0 = m0 & 2047;
                const int m1 = m0 + 8;
                const int bb1 = m1 >> 11, ss1 = m1 & 2047;
                const size_t i0 = (((size_t)bb0 * NH_ + hh) * SQ_ + ss0) * HD_ + dd;
                const size_t i1 = (((size_t)bb1 * NH_ + hh) * SQ_ + ss1) * HD_ + dd;
                uint32_t p01 = packbf(f0, f1);
                uint32_t p23 = packbf(f2, f3);
                uint32_t r01 = packbf(f0 - lowbf(p01), f1 - highbf(p01));
                uint32_t r23 = packbf(f2 - lowbf(p23), f3 - highbf(p23));
                *(uint32_t*)(outH + i0) = p01;
                *(uint32_t*)(outL + i0) = r01;
                *(uint32_t*)(outH + i1) = p23;
                *(uint32_t*)(outL + i1) = r23;
            }
        }
    }
}

// ===========================================================================
// Flash attention via mma.sync (validated R15, unchanged).
// ===========================================================================
#define AT_QH 0
#define AT_QL (AT_QH + 16384)
#define AT_KH (AT_QL + 16384)
#define AT_KL (AT_KH + 16384)
#define AT_VH (AT_KL + 16384)
#define AT_VL (AT_VH + 16384)
#define AT_SMEM (AT_VL + 16384)   /* 98304 bytes */

__global__ __launch_bounds__(256, 1)
void attn_mma(const __nv_bfloat16* __restrict__ Qh_, const __nv_bfloat16* __restrict__ Ql_,
              const __nv_bfloat16* __restrict__ Kh_, const __nv_bfloat16* __restrict__ Kl_,
              const __nv_bfloat16* __restrict__ Vh_, const __nv_bfloat16* __restrict__ Vl_,
              const float* __restrict__ mask, float* __restrict__ ctx)
{
    extern __shared__ char smem[];
    const uint32_t sb = smem_to_u32(smem);
    const int tid = threadIdx.x, wid = tid >> 5, lane = tid & 31;
    const int h = blockIdx.x, q0 = blockIdx.y << 7, b = blockIdx.z;
    const size_t bh = (size_t)b * NH_ + h;

    const __nv_bfloat16* Qhp = Qh_ + (bh * SQ_ + q0) * HD_;
    const __nv_bfloat16* Qlp = Ql_ + (bh * SQ_ + q0) * HD_;
    const __nv_bfloat16* Khp = Kh_ + bh * SKV_ * HD_;
    const __nv_bfloat16* Klp = Kl_ + bh * SKV_ * HD_;
    const __nv_bfloat16* Vhp = Vh_ + bh * SKV_ * HD_;
    const __nv_bfloat16* Vlp = Vl_ + bh * SKV_ * HD_;

    // load Q tiles (swizzled)
    for (int idx = tid; idx < 1024; idx += 256) {
        const int r = idx >> 3, cu = idx & 7;
        const uint32_t so = SMEM_SWIZZLE_128B((uint32_t)(r * 128 + cu * 16));
        const int g = r * HD_ + cu * 8;
        *(uint4*)(smem + AT_QH + so) = *(const uint4*)(Qhp + g);
        *(uint4*)(smem + AT_QL + so) = *(const uint4*)(Qlp + g);
    }
    __syncthreads();

    const uint32_t sxor = (uint32_t)((lane & 7) << 4);

    const int a_rl = (lane & 7) + ((lane >> 3) & 1) * 8;
    const int a_k  = (lane >> 4) * 8;
    uint32_t qh[4][4], ql[4][4];
#pragma unroll
    for (int c = 0; c < 4; c++) {
        const uint32_t off = (uint32_t)(wid * 16 + a_rl) * 128u
                           + (((uint32_t)((c * 16 + a_k) * 2)) ^ sxor);
        ldsm4(qh[c], sb + AT_QH + off);
        ldsm4(ql[c], sb + AT_QL + off);
    }

    const int r0 = wid * 16 + (lane >> 2);
    const float* mp0 = mask + ((size_t)b * SQ_ + q0 + r0) * SKV_ + (lane & 3) * 2;
    const float* mp1 = mp0 + 8 * SKV_;

    float o[8][4];
#pragma unroll
    for (int j = 0; j < 8; j++) { o[j][0] = o[j][1] = o[j][2] = o[j][3] = 0.f; }
    float m0 = -1e30f, m1 = -1e30f, l0 = 0.f, l1 = 0.f;

    const int b_rl = (lane & 7) + (lane >> 4) * 8;
    const int b_k  = ((lane >> 3) & 1) * 8;
    const int v_r  = lane & 15;
    const int v_c  = (lane >> 4) * 16;

    for (int t = 0; t < 16; t++) {
        __syncthreads();
        const __nv_bfloat16* kh_t = Khp + (size_t)(t << 7) * HD_;
        const __nv_bfloat16* kl_t = Klp + (size_t)(t << 7) * HD_;
        const __nv_bfloat16* vh_t = Vhp + (size_t)(t << 7) * HD_;
        const __nv_bfloat16* vl_t = Vlp + (size_t)(t << 7) * HD_;
        for (int idx = tid; idx < 1024; idx += 256) {
            const int r = idx >> 3, cu = idx & 7;
            const uint32_t so = SMEM_SWIZZLE_128B((uint32_t)(r * 128 + cu * 16));
            const int g = r * HD_ + cu * 8;
            *(uint4*)(smem + AT_KH + so) = *(const uint4*)(kh_t + g);
            *(uint4*)(smem + AT_KL + so) = *(const uint4*)(kl_t + g);
            *(uint4*)(smem + AT_VH + so) = *(const uint4*)(vh_t + g);
            *(uint4*)(smem + AT_VL + so) = *(const uint4*)(vl_t + g);
        }
        __syncthreads();

        float s[16][4];
#pragma unroll
        for (int j = 0; j < 16; j++) { s[j][0] = s[j][1] = s[j][2] = s[j][3] = 0.f; }

#pragma unroll
        for (int c = 0; c < 4; c++) {
            const uint32_t kc = ((uint32_t)((c * 16 + b_k) * 2)) ^ sxor;
#pragma unroll
            for (int jp = 0; jp < 8; jp++) {
                uint32_t kh[4], kl[4];
                const uint32_t off = (uint32_t)(jp * 16 + b_rl) * 128u + kc;
                ldsm4(kh, sb + AT_KH + off);
                ldsm4(kl, sb + AT_KL + off);
                mma16816(s[2 * jp],     qh[c], kh);
                mma16816(s[2 * jp],     qh[c], kl);
                mma16816(s[2 * jp],     ql[c], kh);
                mma16816(s[2 * jp + 1], qh[c], kh + 2);
                mma16816(s[2 * jp + 1], qh[c], kl + 2);
                mma16816(s[2 * jp + 1], ql[c], kh + 2);
            }
        }

        const float* q0m = mp0 + (t << 7);
        const float* q1m = mp1 + (t << 7);
#pragma unroll
        for (int j = 0; j < 16; j++) {
            float2 u0 = *(const float2*)(q0m + j * 8);
            float2 u1 = *(const float2*)(q1m + j * 8);
            s[j][0] = fmaf(u0.x - 1.f, MC_F, s[j][0]);
            s[j][1] = fmaf(u0.y - 1.f, MC_F, s[j][1]);
            s[j][2] = fmaf(u1.x - 1.f, MC_F, s[j][2]);
            s[j][3] = fmaf(u1.y - 1.f, MC_F, s[j][3]);
        }

        float mx0 = s[0][0], mx1 = s[0][2];
#pragma unroll
        for (int j = 0; j < 16; j++) {
            mx0 = fmaxf(mx0, fmaxf(s[j][0], s[j][1]));
            mx1 = fmaxf(mx1, fmaxf(s[j][2], s[j][3]));
        }
        mx0 = fmaxf(mx0, __shfl_xor_sync(0xffffffffu, mx0, 1));
        mx0 = fmaxf(mx0, __shfl_xor_sync(0xffffffffu, mx0, 2));
        mx1 = fmaxf(mx1, __shfl_xor_sync(0xffffffffu, mx1, 1));
        mx1 = fmaxf(mx1, __shfl_xor_sync(0xffffffffu, mx1, 2));

        const float nm0 = fmaxf(m0, mx0), nm1 = fmaxf(m1, mx1);
        const float a0 = exp2p(m0 - nm0), a1 = exp2p(m1 - nm1);
        m0 = nm0; m1 = nm1;

        float rs0 = 0.f, rs1 = 0.f;
#pragma unroll
        for (int j = 0; j < 16; j++) {
            s[j][0] = exp2p(s[j][0] - m0);
            s[j][1] = exp2p(s[j][1] - m0);
            s[j][2] = exp2p(s[j][2] - m1);
            s[j][3] = exp2p(s[j][3] - m1);
            rs0 += s[j][0] + s[j][1];
            rs1 += s[j][2] + s[j][3];
        }
        rs0 += __shfl_xor_sync(0xffffffffu, rs0, 1);
        rs0 += __shfl_xor_sync(0xffffffffu, rs0, 2);
        rs1 += __shfl_xor_sync(0xffffffffu, rs1, 1);
        rs1 += __shfl_xor_sync(0xffffffffu, rs1, 2);
        l0 = l0 * a0 + rs0;
        l1 = l1 * a1 + rs1;

#pragma unroll
        for (int j = 0; j < 8; j++) {
            o[j][0] *= a0; o[j][1] *= a0;
            o[j][2] *= a1; o[j][3] *= a1;
        }

#pragma unroll
        for (int c = 0; c < 8; c++) {
            uint32_t ph[4], pl[4];
            ph[0] = packbf(s[2 * c][0],     s[2 * c][1]);
            ph[1] = packbf(s[2 * c][2],     s[2 * c][3]);
            ph[2] = packbf(s[2 * c + 1][0], s[2 * c + 1][1]);
            ph[3] = packbf(s[2 * c + 1][2], s[2 * c + 1][3]);
            pl[0] = packbf(s[2 * c][0] - lowbf(ph[0]),     s[2 * c][1] - highbf(ph[0]));
            pl[1] = packbf(s[2 * c][2] - lowbf(ph[1]),     s[2 * c][3] - highbf(ph[1]));
            pl[2] = packbf(s[2 * c + 1][0] - lowbf(ph[2]), s[2 * c + 1][1] - highbf(ph[2]));
            pl[3] = packbf(s[2 * c + 1][2] - lowbf(ph[3]), s[2 * c + 1][3] - highbf(ph[3]));

            const uint32_t vrow = (uint32_t)(c * 16 + v_r) * 128u;
#pragma unroll
            for (int dg = 0; dg < 4; dg++) {
                uint32_t vh[4], vl[4];
                const uint32_t off = vrow + (((uint32_t)(v_c + dg * 32)) ^ sxor);
                ldsm4t(vh, sb + AT_VH + off);
                ldsm4t(vl, sb + AT_VL + off);
                mma16816(o[2 * dg],     ph, vh);
                mma16816(o[2 * dg],     ph, vl);
                mma16816(o[2 * dg],     pl, vh);
                mma16816(o[2 * dg + 1], ph, vh + 2);
                mma16816(o[2 * dg + 1], ph, vl + 2);
                mma16816(o[2 * dg + 1], pl, vh + 2);
            }
        }
    }

    const float i0 = 1.f / l0, i1 = 1.f / l1;
    float* c0 = ctx + ((size_t)b * SQ_ + q0 + r0) * H_ + h * HD_ + (lane & 3) * 2;
    float* c1 = c0 + 8 * H_;
#pragma unroll
    for (int j = 0; j < 8; j++) {
        *(float2*)(c0 + j * 8) = make_float2(o[j][0] * i0, o[j][1] * i0);
        *(float2*)(c1 + j * 8) = make_float2(o[j][2] * i1, o[j][3] * i1);
    }
}

// ===========================================================================
extern "C" void kernel_launch(void* const* d_in, const int* in_sizes, int n_in,
                              void* d_out, int out_size)
{
    (void)in_sizes; (void)n_in; (void)out_size;
    const float* xq  = (const float*)d_in[0];
    const float* xkv = (const float*)d_in[1];
    const float* msk = (const float*)d_in[2];
    const float* Wq  = (const float*)d_in[3];
    const float* bq  = (const float*)d_in[4];
    const float* Wk  = (const float*)d_in[5];
    const float* Wv  = (const float*)d_in[6];
    const float* bv  = (const float*)d_in[7];
    const float* Wo  = (const float*)d_in[8];
    const float* bo  = (const float*)d_in[9];
    float* out = (float*)d_out;

    float* ctx;
    cudaGetSymbolAddress((void**)&ctx, g_ctx);

    __nv_bfloat16 *qh, *ql, *kh, *kl, *vh, *vl;
    cudaGetSymbolAddress((void**)&qh, g_qh); cudaGetSymbolAddress((void**)&ql, g_ql);
    cudaGetSymbolAddress((void**)&kh, g_kh); cudaGetSymbolAddress((void**)&kl, g_kl);
    cudaGetSymbolAddress((void**)&vh, g_vh); cudaGetSymbolAddress((void**)&vl, g_vl);

    __nv_bfloat16 *xqh, *xql, *xkvh, *xkvl, *wqh, *wql, *wkh, *wkl, *wvh, *wvl, *woh, *wol, *cth, *ctl;
    cudaGetSymbolAddress((void**)&xqh,  g_xq_h);  cudaGetSymbolAddress((void**)&xql,  g_xq_l);
    cudaGetSymbolAddress((void**)&xkvh, g_xkv_h); cudaGetSymbolAddress((void**)&xkvl, g_xkv_l);
    cudaGetSymbolAddress((void**)&wqh,  g_wq_h);  cudaGetSymbolAddress((void**)&wql,  g_wq_l);
    cudaGetSymbolAddress((void**)&wkh,  g_wk_h);  cudaGetSymbolAddress((void**)&wkl,  g_wk_l);
    cudaGetSymbolAddress((void**)&wvh,  g_wv_h);  cudaGetSymbolAddress((void**)&wvl,  g_wv_l);
    cudaGetSymbolAddress((void**)&woh,  g_wo_h);  cudaGetSymbolAddress((void**)&wol,  g_wo_l);
    cudaGetSymbolAddress((void**)&cth,  g_ctx_h); cudaGetSymbolAddress((void**)&ctl,  g_ctx_l);

    cudaFuncSetAttribute(proj_mma, cudaFuncAttributeMaxDynamicSharedMemorySize, PROJ_SMEM);
    cudaFuncSetAttribute(attn_mma, cudaFuncAttributeMaxDynamicSharedMemorySize, AT_SMEM);

    const int nX = M_ * K_;
    const int nW = H_ * K_;
    split_kernel<<<nX / 4 / 256, 256>>>(xq,  xqh,  xql,  nX);
    split_kernel<<<nX / 4 / 256, 256>>>(xkv, xkvh, xkvl, nX);
    split_kernel<<<nW / 4 / 256, 256>>>(Wq,  wqh,  wql,  nW);
    split_kernel<<<nW / 4 / 256, 256>>>(Wk,  wkh,  wkl,  nW);
    split_kernel<<<nW / 4 / 256, 256>>>(Wv,  wvh,  wvl,  nW);
    split_kernel<<<nW / 4 / 256, 256>>>(Wo,  woh,  wol,  nW);

    dim3 pg(H_ / 128, M_ / 128);
    proj_mma<<<pg, 256, PROJ_SMEM>>>(xqh,  xql,  wqh, wql, bq,      nullptr, qh, ql, QSCALE_F, 1);
    proj_mma<<<pg, 256, PROJ_SMEM>>>(xkvh, xkvl, wkh, wkl, nullptr, nullptr, kh, kl, 1.0f,     1);
    proj_mma<<<pg, 256, PROJ_SMEM>>>(xkvh, xkvl, wvh, wvl, bv,      nullptr, vh, vl, 1.0f,     1);

    attn_mma<<<dim3(NH_, SQ_ / 128, B_), 256, AT_SMEM>>>(qh, ql, kh, kl, vh, vl, msk, ctx);

    split_kernel<<<nX / 4 / 256, 256>>>(ctx, cth, ctl, nX);
    proj_mma<<<pg, 256, PROJ_SMEM>>>(cth, ctl, woh, wol, bo, out, nullptr, nullptr, 1.0f, 0);
}